// round 14
// baseline (speedup 1.0000x reference)
#include <cuda_runtime.h>
#include <math.h>
#include <stdint.h>

#define NB 4096
#define NC 128
#define KC 32
#define MATSZ 16777216ULL   // 4096*4096
#define NT 512

__device__ float d_partial[NC];
__device__ unsigned d_ticket;   // zero-init; last block resets

typedef unsigned long long u64;

__device__ __forceinline__ u64 fma2(u64 a, u64 b, u64 c) {
    u64 d;
    asm("fma.rn.f32x2 %0, %1, %2, %3;" : "=l"(d) : "l"(a), "l"(b), "l"(c));
    return d;
}
#define PK2(v, lo, hi)   asm("mov.b64 %0, {%1, %2};" : "=l"(v) : "f"(lo), "f"(hi))
#define UNPK2(lo, hi, v) asm("mov.b64 {%0, %1}, %2;" : "=f"(lo), "=f"(hi) : "l"(v))

__device__ __forceinline__ uint32_t f2tf(float f) {
    uint32_t r;
    asm("cvt.rna.tf32.f32 %0, %1;" : "=r"(r) : "f"(f));
    return r;
}
#define MMA_TF32(d0, d1, d2, d3, a0, a1, a2, a3, b0, b1) \
    asm volatile("mma.sync.aligned.m16n8k8.row.col.f32.tf32.tf32.f32 " \
                 "{%0,%1,%2,%3}, {%4,%5,%6,%7}, {%8,%9}, {%0,%1,%2,%3};" \
                 : "+f"(d0), "+f"(d1), "+f"(d2), "+f"(d3) \
                 : "r"(a0), "r"(a1), "r"(a2), "r"(a3), "r"(b0), "r"(b1))

#define BSYNC256(id)  asm volatile("bar.sync %0, %1;"   :: "n"(id), "n"(256) : "memory")
#define BARRIVE512(id) asm volatile("bar.arrive %0, %1;" :: "n"(id), "n"(512) : "memory")
#define BARSYNC512(id) asm volatile("bar.sync %0, %1;"   :: "n"(id), "n"(512) : "memory")

// ---- dynamic smem word offsets -------------------------------------------
#define SCRATCH 0       // 8448 w: w1 staging (stride 260) during hij (w0-7 only)
#define EMBT   8448     // 4224 w  embT[k*33 + r]
#define PST    12672    // 4224 w  psw1T[e*33 + m]
#define W2FRAG 16896    // 8192 w: B fragments [(tp*8+nt)*32+lane] uint4
#define HIT    25088    // 4224 w  hiT[k*33 + i]
#define HJT    29312    // 4224 w  hjT[k*33 + j]  (cv merged at store)
#define DISTW  33536    // 1024
#define EFFW   34560    // 1024
#define PFW    35584    // 1024
#define FLOWW  36608    // 1024
#define W1DW   37632    // 128
#define CVW    37760    // 128
#define B2FW   37888    // 64
#define W3FW   37952    // 64
#define GIDX   38016    // int[32]
#define NETW   38048
#define PRIOW  38080
#define ORDW   38112
#define ACTBW  38144
#define DNETW  38176
#define NSRTW  38208
#define RSENTW 38240
#define WCNTW  38272    // int[16]
#define POSW   38288    // float2[32] = 64 w (8B aligned)
#define SM_WORDS 38360
#define SM_BYTES (SM_WORDS * 4)
#define W1STRIDE 260

__global__ void __launch_bounds__(NT, 1) mega_kernel(
    const float* __restrict__ emb,  const float* __restrict__ gen,
    const float* __restrict__ cons, const float* __restrict__ pos,
    const float* __restrict__ fpw1, const float* __restrict__ fpb1,
    const float* __restrict__ fpw2, const float* __restrict__ fpb2,
    const float* __restrict__ fpw3, const float* __restrict__ fpb3,
    const float* __restrict__ enw1, const float* __restrict__ enb1,
    const float* __restrict__ enw2, const float* __restrict__ enb2,
    const float* __restrict__ psw1, const float* __restrict__ psb1,
    const float* __restrict__ psw2, const float* __restrict__ psb2,
    const int* __restrict__ assign, const int* __restrict__ hour_p,
    float* __restrict__ out) {
    extern __shared__ float smf[];
    int* s_gidx = (int*)(smf + GIDX);
    int* s_ord  = (int*)(smf + ORDW);
    unsigned* s_actb = (unsigned*)(smf + ACTBW);
    int* s_wcnt = (int*)(smf + WCNTW);
    float2* s_pos2 = (float2*)(smf + POSW);

    const int c = blockIdx.x;
    const int t = threadIdx.x;
    const int w = t >> 5, lane = t & 31;
    const int hour = hour_p ? *hour_p : 12;

    // ================= A. stable grouping (16 warps, 2-pass ballot) ========
    {
        int a[8];
        const int* ap = assign + w * 256;
#pragma unroll
        for (int q = 0; q < 8; q++) a[q] = ap[q * 32 + lane];
        unsigned balls[8];
        int cnt = 0;
#pragma unroll
        for (int q = 0; q < 8; q++) {
            balls[q] = __ballot_sync(0xffffffffu, a[q] == c);
            cnt += __popc(balls[q]);
        }
        if (lane == 0) s_wcnt[w] = cnt;
        __syncthreads();
        int run = 0;
        for (int ww = 0; ww < 16; ww++) if (ww < w) run += s_wcnt[ww];
#pragma unroll
        for (int q = 0; q < 8; q++) {
            if (a[q] == c) {
                int p = run + __popc(balls[q] & ((1u << lane) - 1u));
                if (p < KC) s_gidx[p] = w * 256 + q * 32 + lane;
            }
            run += __popc(balls[q]);
        }
    }
    __syncthreads();
    float b3 = fpb3[0];

    if (w >= 8) {
        // ============ warps 8-15: quick staging, arrive, then fill =========
        const int t2 = t - 256;            // 0..255
        if (t2 < 32) {
            int b = s_gidx[t2];
            smf[NETW + t2] = gen[b * 24 + hour] - cons[b * 24 + hour];
            s_pos2[t2] = make_float2(pos[b * 2], pos[b * 2 + 1]);
        }
        if (t2 < 128) {
            float hour_f = (float)hour * (1.f / 24.f);
            int k = t2;
            smf[W1DW + k] = fpw1[(size_t)k * 258 + 256];
            smf[CVW + k] = fmaf(hour_f, fpw1[(size_t)k * 258 + 257], fpb1[k]);
        } else if (t2 < 192) {
            int n = t2 - 128;
            smf[B2FW + n] = fpb2[n];
            smf[W3FW + n] = fpw3[n];
        }
        for (int i = t2; i < 4096; i += 256) {
            int m = i >> 7, e = i & 127;
            smf[PST + e * 33 + m] = psw1[i];
        }
        {
            uint4* bf = (uint4*)(smf + W2FRAG);
            for (int idx = t2; idx < 2048; idx += 256) {
                int tp = idx >> 8;
                int rem = idx & 255;
                int nt = rem >> 5, l2 = rem & 31;
                int n = nt * 8 + (l2 >> 2);
                int kb = tp * 16 + (l2 & 3);
                const float* wrow = fpw2 + n * 128 + kb;
                uint4 v;
                v.x = f2tf(__ldg(wrow));
                v.y = f2tf(__ldg(wrow + 4));
                v.z = f2tf(__ldg(wrow + 8));
                v.w = f2tf(__ldg(wrow + 12));
                bf[idx] = v;
            }
        }
        BSYNC256(6);   // pos visible within warps 8-15
        {
            float b2v = enb2[0];
            for (int pp = t2; pp < 1024; pp += 256) {
                int i = pp >> 5, j = pp & 31;
                float2 pi = s_pos2[i], pj = s_pos2[j];
                float dx = pi.x - pj.x, dy = pi.y - pj.y;
                float dist = sqrtf(dx * dx + dy * dy);
                float tq = dist * (1.f / 1000.f);
                float s = 0.f;
#pragma unroll
                for (int l = 0; l < 16; l++)
                    s = fmaf(fmaxf(fmaf(tq, __ldg(enw1 + l), __ldg(enb1 + l)), 0.f),
                             __ldg(enw2 + l), s);
                smf[EFFW + pp] = 0.85f + 0.13f / (1.f + expf(-(s + b2v)));
                smf[DISTW + pp] = dist;
            }
        }
        BARRIVE512(9);   // release consumers; go fill (no blocking)

        const float4 z4 = make_float4(0.f, 0.f, 0.f, 0.f);
        const float4 o4 = make_float4(1.f, 1.f, 1.f, 1.f);
        float4* outS4 = (float4*)out;
        float4* outE4 = (float4*)(out + MATSZ);
#pragma unroll 4
        for (int r = 0; r < 32; r++) {
            size_t rb = (size_t)s_gidx[r] * 1024;
#pragma unroll
            for (int q = 0; q < 4; q++) {
                outS4[rb + q * 256 + t2] = z4;
                outE4[rb + q * 256 + t2] = o4;
            }
        }
    } else {
        // ============ warps 0-7: EMBT gather, prio, hij, mainloop ==========
        // direct-transposed emb gather (coalesced LDG, conflict-free STS)
#pragma unroll
        for (int rr = 0; rr < 4; rr++) {
            int r = w * 4 + rr;
            const float* er = emb + (size_t)s_gidx[r] * 128;
#pragma unroll
            for (int q = 0; q < 4; q++) {
                int k = q * 32 + lane;
                smf[EMBT + k * 33 + r] = __ldg(er + k);
            }
        }
        BSYNC256(5);     // EMBT visible among warps 0-7
        BARSYNC512(9);   // wait for warps 8-15 staging (CVW/PST/DIST/W2FRAG/...)

        // ---- prio (4 rows per warp) ----------------------------------------
        {
            float b1m = psb1[lane], w2m = psw2[lane], b2s = psb2[0];
#pragma unroll
            for (int rr = 0; rr < 4; rr++) {
                int r = w * 4 + rr;
                float acc = b1m;
#pragma unroll 8
                for (int e = 0; e < 128; e++)
                    acc = fmaf(smf[EMBT + e * 33 + r], smf[PST + e * 33 + lane], acc);
                float v = fmaxf(acc, 0.f) * w2m;
#pragma unroll
                for (int o = 16; o > 0; o >>= 1)
                    v += __shfl_xor_sync(0xffffffffu, v, o);
                if (lane == 0) smf[PRIOW + r] = 1.f / (1.f + expf(-(v + b2s)));
            }
        }

        // ---- hij GEMM (lane=row, warp covers 32 out-cols) ------------------
        u64 acc[16];
#pragma unroll
        for (int u = 0; u < 16; u++) acc[u] = 0ull;
        for (int kc = 0; kc < 4; kc++) {
            BSYNC256(5);
#pragma unroll
            for (int q = 0; q < 32; q++) {
                int cc = q * 8 + w;        // out column 0..255
                float v = (cc < 128)
                    ? fpw1[(size_t)cc * 258 + kc * 32 + lane]
                    : fpw1[(size_t)(cc - 128) * 258 + 128 + kc * 32 + lane];
                smf[SCRATCH + lane * W1STRIDE + cc] = v;
            }
            BSYNC256(5);
            const u64* w1u = (const u64*)(smf + SCRATCH);
#pragma unroll 4
            for (int kk = 0; kk < 32; kk++) {
                int k = kc * 32 + kk;
                float e = smf[EMBT + k * 33 + lane];
                u64 e2; PK2(e2, e, e);
                const ulonglong2* wr =
                    (const ulonglong2*)(w1u + kk * (W1STRIDE / 2) + w * 16);
#pragma unroll
                for (int h = 0; h < 8; h++) {
                    ulonglong2 qq = wr[h];
                    acc[2 * h]     = fma2(e2, qq.x, acc[2 * h]);
                    acc[2 * h + 1] = fma2(e2, qq.y, acc[2 * h + 1]);
                }
            }
        }
#pragma unroll
        for (int u = 0; u < 16; u++) {
            int pc = w * 16 + u;           // out-col pair (2pc, 2pc+1)
            float lo, hi;
            UNPK2(lo, hi, acc[u]);
            if (pc < 64) {
                smf[HIT + (2 * pc) * 33 + lane] = lo;
                smf[HIT + (2 * pc + 1) * 33 + lane] = hi;
            } else {
                int k = 2 * pc - 128;
                smf[HJT + k * 33 + lane] = lo + smf[CVW + k];
                smf[HJT + (k + 1) * 33 + lane] = hi + smf[CVW + k + 1];
            }
        }
        BSYNC256(5);     // HIT/HJT visible among warps 0-7

        // ---- mainloop: inline-A tf32 mma, 8 warps x 8 strip tasks ----------
        const int g = lane >> 2, l4 = lane & 3;
        const int sid = w >> 1;
        const int jl = (w & 1) * 16 + g;
        const int jh = jl + 8;
        const uint4* bfrag = (const uint4*)(smf + W2FRAG);

        for (int it = 0; it < 8; it++) {
            const int isend = 4 * it + sid;
            float ddl = smf[DISTW + isend * 32 + jl];
            float ddh = smf[DISTW + isend * 32 + jh];
            float facc[8][4];
#pragma unroll
            for (int nt = 0; nt < 8; nt++) {
                facc[nt][0] = 0.f; facc[nt][1] = 0.f;
                facc[nt][2] = 0.f; facc[nt][3] = 0.f;
            }
#pragma unroll
            for (int tp = 0; tp < 8; tp++) {
                int kb = tp * 16 + l4;
                float w0 = smf[W1DW + kb],      w1v = smf[W1DW + kb + 4];
                float w2v = smf[W1DW + kb + 8], w3v = smf[W1DW + kb + 12];
                float hi0 = smf[HIT + kb * 33 + isend];
                float hi1 = smf[HIT + (kb + 4) * 33 + isend];
                float hi2 = smf[HIT + (kb + 8) * 33 + isend];
                float hi3 = smf[HIT + (kb + 12) * 33 + isend];
                float hl0 = smf[HJT + kb * 33 + jl];
                float hl1 = smf[HJT + (kb + 4) * 33 + jl];
                float hl2 = smf[HJT + (kb + 8) * 33 + jl];
                float hl3 = smf[HJT + (kb + 12) * 33 + jl];
                float hh0 = smf[HJT + kb * 33 + jh];
                float hh1 = smf[HJT + (kb + 4) * 33 + jh];
                float hh2 = smf[HJT + (kb + 8) * 33 + jh];
                float hh3 = smf[HJT + (kb + 12) * 33 + jh];
                uint32_t a0 = f2tf(fmaxf(hi0 + fmaf(ddl, w0, hl0), 0.f));
                uint32_t a1 = f2tf(fmaxf(hi0 + fmaf(ddh, w0, hh0), 0.f));
                uint32_t a2 = f2tf(fmaxf(hi1 + fmaf(ddl, w1v, hl1), 0.f));
                uint32_t a3 = f2tf(fmaxf(hi1 + fmaf(ddh, w1v, hh1), 0.f));
                uint32_t a4 = f2tf(fmaxf(hi2 + fmaf(ddl, w2v, hl2), 0.f));
                uint32_t a5 = f2tf(fmaxf(hi2 + fmaf(ddh, w2v, hh2), 0.f));
                uint32_t a6 = f2tf(fmaxf(hi3 + fmaf(ddl, w3v, hl3), 0.f));
                uint32_t a7 = f2tf(fmaxf(hi3 + fmaf(ddh, w3v, hh3), 0.f));
                const uint4* bp = bfrag + tp * 256 + lane;
#pragma unroll
                for (int nt = 0; nt < 8; nt++) {
                    uint4 bv = bp[nt * 32];
                    MMA_TF32(facc[nt][0], facc[nt][1], facc[nt][2], facc[nt][3],
                             a0, a1, a2, a3, bv.x, bv.y);
                    MMA_TF32(facc[nt][0], facc[nt][1], facc[nt][2], facc[nt][3],
                             a4, a5, a6, a7, bv.z, bv.w);
                }
            }
            // epilogue: relu(+b2) dot w3 over 64 n, quad reduce, softplus
            float vlo = 0.f, vhi = 0.f;
#pragma unroll
            for (int nt = 0; nt < 8; nt++) {
                int n0 = nt * 8 + 2 * l4;
                float b2a = smf[B2FW + n0], b2b = smf[B2FW + n0 + 1];
                float w3a = smf[W3FW + n0], w3b = smf[W3FW + n0 + 1];
                vlo = fmaf(fmaxf(facc[nt][0] + b2a, 0.f), w3a, vlo);
                vlo = fmaf(fmaxf(facc[nt][1] + b2b, 0.f), w3b, vlo);
                vhi = fmaf(fmaxf(facc[nt][2] + b2a, 0.f), w3a, vhi);
                vhi = fmaf(fmaxf(facc[nt][3] + b2b, 0.f), w3b, vhi);
            }
            vlo += __shfl_xor_sync(0xffffffffu, vlo, 1);
            vlo += __shfl_xor_sync(0xffffffffu, vlo, 2);
            vhi += __shfl_xor_sync(0xffffffffu, vhi, 1);
            vhi += __shfl_xor_sync(0xffffffffu, vhi, 2);
            if (l4 == 0) {
                float x = vlo + b3;
                smf[PFW + isend * 32 + jl] = (x > 20.f) ? x : log1pf(expf(x));
                x = vhi + b3;
                smf[PFW + isend * 32 + jh] = (x > 20.f) ? x : log1pf(expf(x));
            }
        }
    }
    __syncthreads();

    // ================= D. greedy (warp 0, prefix-scan water-filling) =======
    if (w == 0) {
        float pr = smf[PRIOW + lane];
        int r = 0;
#pragma unroll
        for (int l = 0; l < KC; l++) {
            float q = smf[PRIOW + l];
            r += (q > pr) || (q == pr && l < lane);
        }
        s_ord[r] = lane;
        __syncwarp();
        int oj = s_ord[lane];
        float nets = smf[NETW + oj];
        float dn = nets;
        for (int i = 0; i < 32; i++) {
            int oi = s_ord[i];
            float A = fmaxf(__shfl_sync(0xffffffffu, nets, i), 0.f);
            float needed = -dn;
            float pf = smf[PFW + oi * 32 + oj];
            float cap = (needed > 0.f) ? fminf(needed, pf) : 0.f;
            float C = cap;
#pragma unroll
            for (int o = 1; o < 32; o <<= 1) {
                float x = __shfl_up_sync(0xffffffffu, C, o);
                if (lane >= o) C += x;
            }
            float Cprev = C - cap;
            float avail = A - Cprev;
            bool act = (avail > 0.f) && (needed > 0.f);
            float f = act ? fminf(fminf(avail, needed), pf) : 0.f;
            dn += f * smf[EFFW + oi * 32 + oj];
            smf[FLOWW + i * 32 + lane] = f;
            unsigned ab = __ballot_sync(0xffffffffu, act);
            if (lane == 0) s_actb[i] = ab;
        }
        smf[DNETW + lane] = dn;
        smf[NSRTW + lane] = nets;
    }
    __syncthreads();

    // ================= E. scatter (16 warps x 2 rows) ======================
    {
        float* out_sh = out;
        float* out_ef = out + MATSZ;
        float* out_sent = out + 2 * MATSZ + 1;
        float* out_recv = out_sent + NB;
        float* out_na = out_recv + NB;
        int oj = s_ord[lane];
        int gj = s_gidx[oj];
#pragma unroll
        for (int rr = 0; rr < 2; rr++) {
            int srow = w * 2 + rr;
            int oi = s_ord[srow];
            int gi = s_gidx[oi];
            float f = smf[FLOWW + srow * 32 + lane];
            unsigned ab = s_actb[srow];
            if ((ab >> lane) & 1u) {
                out_sh[(size_t)gi * NB + gj] = f;
                out_ef[(size_t)gi * NB + gj] = smf[EFFW + oi * 32 + oj];
            }
            float v = f;
#pragma unroll
            for (int o = 16; o > 0; o >>= 1) v += __shfl_xor_sync(0xffffffffu, v, o);
            if (lane == 0) {
                out_sent[gi] = v;
                float dnl = smf[DNETW + srow];
                out_recv[gi] = dnl - smf[NSRTW + srow];
                out_na[gi] = dnl;
                smf[RSENTW + srow] = v;
            }
        }
    }
    __syncthreads();

    // ================= F. per-cluster total + last-block global sum ========
    if (t == 0) {
        float tot = 0.f;
#pragma unroll
        for (int i = 0; i < 32; i++) tot += smf[RSENTW + i];
        d_partial[c] = tot;
        __threadfence();
        unsigned old = atomicAdd(&d_ticket, 1u);
        if (old == NC - 1) {
            __threadfence();
            float s0 = 0.f, s1 = 0.f, s2 = 0.f, s3 = 0.f;
#pragma unroll 8
            for (int q = 0; q < NC; q += 4) {
                s0 += __ldcg(d_partial + q);
                s1 += __ldcg(d_partial + q + 1);
                s2 += __ldcg(d_partial + q + 2);
                s3 += __ldcg(d_partial + q + 3);
            }
            out[2 * MATSZ] = (s0 + s1) + (s2 + s3);
            d_ticket = 0;
        }
    }
}

// ------------------------------------------------------------------------------
extern "C" void kernel_launch(void* const* d_in, const int* in_sizes, int n_in,
                              void* d_out, int out_size) {
    const float* emb   = (const float*)d_in[0];
    const float* gen   = (const float*)d_in[1];
    const float* cons  = (const float*)d_in[2];
    const float* pos   = (const float*)d_in[3];
    const float* fpw1  = (const float*)d_in[4];
    const float* fpb1  = (const float*)d_in[5];
    const float* fpw2  = (const float*)d_in[6];
    const float* fpb2  = (const float*)d_in[7];
    const float* fpw3  = (const float*)d_in[8];
    const float* fpb3  = (const float*)d_in[9];
    const float* enw1  = (const float*)d_in[10];
    const float* enb1  = (const float*)d_in[11];
    const float* enw2  = (const float*)d_in[12];
    const float* enb2  = (const float*)d_in[13];
    const float* psw1  = (const float*)d_in[14];
    const float* psb1  = (const float*)d_in[15];
    const float* psw2  = (const float*)d_in[16];
    const float* psb2  = (const float*)d_in[17];
    const int*   assign = (const int*)d_in[18];
    const int*   hour   = (n_in >= 21) ? (const int*)d_in[20] : nullptr;
    float* out = (float*)d_out;

    cudaFuncSetAttribute(mega_kernel,
                         cudaFuncAttributeMaxDynamicSharedMemorySize, SM_BYTES);

    mega_kernel<<<NC, NT, SM_BYTES>>>(emb, gen, cons, pos,
                                      fpw1, fpb1, fpw2, fpb2, fpw3, fpb3,
                                      enw1, enb1, enw2, enb2,
                                      psw1, psb1, psw2, psb2,
                                      assign, hour, out);
}

// round 15
// speedup vs baseline: 1.1539x; 1.1539x over previous
#include <cuda_runtime.h>
#include <math.h>
#include <stdint.h>

#define NB 4096
#define NC 128
#define KC 32
#define MATSZ 16777216ULL   // 4096*4096
#define NT 512

__device__ float d_partial[NC];
__device__ unsigned d_ticket;   // zero-init; last block resets

typedef unsigned long long u64;

__device__ __forceinline__ u64 fma2(u64 a, u64 b, u64 c) {
    u64 d;
    asm("fma.rn.f32x2 %0, %1, %2, %3;" : "=l"(d) : "l"(a), "l"(b), "l"(c));
    return d;
}
#define PK2(v, lo, hi)   asm("mov.b64 %0, {%1, %2};" : "=l"(v) : "f"(lo), "f"(hi))
#define UNPK2(lo, hi, v) asm("mov.b64 {%0, %1}, %2;" : "=f"(lo), "=f"(hi) : "l"(v))

__device__ __forceinline__ uint32_t f2tf(float f) {
    uint32_t r;
    asm("cvt.rna.tf32.f32 %0, %1;" : "=r"(r) : "f"(f));
    return r;
}
#define MMA_TF32(d0, d1, d2, d3, a0, a1, a2, a3, b0, b1) \
    asm volatile("mma.sync.aligned.m16n8k8.row.col.f32.tf32.tf32.f32 " \
                 "{%0,%1,%2,%3}, {%4,%5,%6,%7}, {%8,%9}, {%0,%1,%2,%3};" \
                 : "+f"(d0), "+f"(d1), "+f"(d2), "+f"(d3) \
                 : "r"(a0), "r"(a1), "r"(a2), "r"(a3), "r"(b0), "r"(b1))

// streaming store (evict-first) for the bulk default fills
__device__ __forceinline__ void stg_cs4(float4* p, float4 v) {
    asm volatile("st.global.cs.v4.f32 [%0], {%1, %2, %3, %4};"
                 :: "l"(p), "f"(v.x), "f"(v.y), "f"(v.z), "f"(v.w) : "memory");
}

#define BSYNC256(id) asm volatile("bar.sync %0, %1;" :: "n"(id), "n"(256) : "memory")

// ---- dynamic smem word offsets -------------------------------------------
#define SCRATCH 0       // 8448 w: emb rows (stride 129) -> w1 staging (stride 260)
#define EMBT   8448     // 4224 w  embT[k*33 + r]
#define PST    12672    // 4224 w  psw1T[e*33 + m]
#define W2FRAG 16896    // 8192 w: B fragments [(tp*8+nt)*32+lane] uint4
#define HIT    25088    // 4224 w  hiT[k*33 + i]
#define HJT    29312    // 4224 w  hjT[k*33 + j]  (cv merged at store)
#define DISTW  33536    // 1024
#define EFFW   34560    // 1024
#define PFW    35584    // 1024
#define FLOWW  36608    // 1024
#define W1DW   37632    // 128
#define CVW    37760    // 128
#define B2FW   37888    // 64
#define W3FW   37952    // 64
#define GIDX   38016    // int[32]
#define NETW   38048
#define PRIOW  38080
#define ORDW   38112
#define ACTBW  38144
#define DNETW  38176
#define NSRTW  38208
#define RSENTW 38240
#define WCNTW  38272    // int[16]
#define POSW   38288    // float2[32] = 64 w (8B aligned)
#define SM_WORDS 38360
#define SM_BYTES (SM_WORDS * 4)
#define W1STRIDE 260

__global__ void __launch_bounds__(NT, 1) mega_kernel(
    const float* __restrict__ emb,  const float* __restrict__ gen,
    const float* __restrict__ cons, const float* __restrict__ pos,
    const float* __restrict__ fpw1, const float* __restrict__ fpb1,
    const float* __restrict__ fpw2, const float* __restrict__ fpb2,
    const float* __restrict__ fpw3, const float* __restrict__ fpb3,
    const float* __restrict__ enw1, const float* __restrict__ enb1,
    const float* __restrict__ enw2, const float* __restrict__ enb2,
    const float* __restrict__ psw1, const float* __restrict__ psb1,
    const float* __restrict__ psw2, const float* __restrict__ psb2,
    const int* __restrict__ assign, const int* __restrict__ hour_p,
    float* __restrict__ out) {
    extern __shared__ float smf[];
    int* s_gidx = (int*)(smf + GIDX);
    int* s_ord  = (int*)(smf + ORDW);
    unsigned* s_actb = (unsigned*)(smf + ACTBW);
    int* s_wcnt = (int*)(smf + WCNTW);
    float2* s_pos2 = (float2*)(smf + POSW);

    const int c = blockIdx.x;
    const int t = threadIdx.x;
    const int w = t >> 5, lane = t & 31;
    const int hour = hour_p ? *hour_p : 12;

    // ================= A. stable grouping (16 warps, 2-pass ballot) ========
    {
        int a[8];
        const int* ap = assign + w * 256;
#pragma unroll
        for (int q = 0; q < 8; q++) a[q] = ap[q * 32 + lane];
        unsigned balls[8];
        int cnt = 0;
#pragma unroll
        for (int q = 0; q < 8; q++) {
            balls[q] = __ballot_sync(0xffffffffu, a[q] == c);
            cnt += __popc(balls[q]);
        }
        if (lane == 0) s_wcnt[w] = cnt;
        __syncthreads();
        int run = 0;
        for (int ww = 0; ww < 16; ww++) if (ww < w) run += s_wcnt[ww];
#pragma unroll
        for (int q = 0; q < 8; q++) {
            if (a[q] == c) {
                int p = run + __popc(balls[q] & ((1u << lane) - 1u));
                if (p < KC) s_gidx[p] = w * 256 + q * 32 + lane;
            }
            run += __popc(balls[q]);
        }
    }
    __syncthreads();

    // ================= B. net, positions, cv/w1d/b2/w3, emb stage ==========
    if (t < KC) {
        int b = s_gidx[t];
        smf[NETW + t] = gen[b * 24 + hour] - cons[b * 24 + hour];
        s_pos2[t] = make_float2(pos[b * 2], pos[b * 2 + 1]);
    }
    {
        float hour_f = (float)hour * (1.f / 24.f);
        if (t >= 256 && t < 384) {
            int k = t - 256;
            smf[W1DW + k] = fpw1[(size_t)k * 258 + 256];
            smf[CVW + k] = fmaf(hour_f, fpw1[(size_t)k * 258 + 257], fpb1[k]);
        }
        if (t >= 384 && t < 448) {
            int n = t - 384;
            smf[B2FW + n] = fpb2[n];
            smf[W3FW + n] = fpw3[n];
        }
        for (int i = t; i < 4096; i += NT) {
            int r = i >> 7, k = i & 127;
            smf[SCRATCH + r * 129 + k] = emb[(size_t)s_gidx[r] * 128 + k];
        }
    }
    __syncthreads();
    for (int i = t; i < 4096; i += NT) {
        int k = i >> 5, r = i & 31;
        smf[EMBT + k * 33 + r] = smf[SCRATCH + r * 129 + k];
    }
    __syncthreads();

    // ================= C. forked prologue ==================================
    if (w < 8) {
        // ---- warps 0-7: hij GEMM (lane=row, warp covers 32 out-cols) ------
        u64 acc[16];
#pragma unroll
        for (int u = 0; u < 16; u++) acc[u] = 0ull;
        for (int kc = 0; kc < 4; kc++) {
            BSYNC256(5);
#pragma unroll
            for (int q = 0; q < 32; q++) {
                int cc = q * 8 + w;        // out column 0..255
                float v = (cc < 128)
                    ? fpw1[(size_t)cc * 258 + kc * 32 + lane]
                    : fpw1[(size_t)(cc - 128) * 258 + 128 + kc * 32 + lane];
                smf[SCRATCH + lane * W1STRIDE + cc] = v;
            }
            BSYNC256(5);
            const u64* w1u = (const u64*)(smf + SCRATCH);
#pragma unroll 4
            for (int kk = 0; kk < 32; kk++) {
                int k = kc * 32 + kk;
                float e = smf[EMBT + k * 33 + lane];
                u64 e2; PK2(e2, e, e);
                const ulonglong2* wr =
                    (const ulonglong2*)(w1u + kk * (W1STRIDE / 2) + w * 16);
#pragma unroll
                for (int h = 0; h < 8; h++) {
                    ulonglong2 qq = wr[h];
                    acc[2 * h]     = fma2(e2, qq.x, acc[2 * h]);
                    acc[2 * h + 1] = fma2(e2, qq.y, acc[2 * h + 1]);
                }
            }
        }
#pragma unroll
        for (int u = 0; u < 16; u++) {
            int pc = w * 16 + u;           // out-col pair (2pc, 2pc+1)
            float lo, hi;
            UNPK2(lo, hi, acc[u]);
            if (pc < 64) {
                smf[HIT + (2 * pc) * 33 + lane] = lo;
                smf[HIT + (2 * pc + 1) * 33 + lane] = hi;
            } else {
                int k = 2 * pc - 128;
                smf[HJT + k * 33 + lane] = lo + smf[CVW + k];
                smf[HJT + (k + 1) * 33 + lane] = hi + smf[CVW + k + 1];
            }
        }
    } else {
        // ---- warps 8-15: prio + dist/eff + w2 fragments -------------------
        const int t2 = t - 256;            // 0..255
        for (int i = t2; i < 4096; i += 256) {
            int m = i >> 7, e = i & 127;
            smf[PST + e * 33 + m] = psw1[i];
        }
        BSYNC256(6);
        {
            float b1m = psb1[lane], w2m = psw2[lane], b2s = psb2[0];
#pragma unroll
            for (int rr = 0; rr < 4; rr++) {
                int r = (w - 8) * 4 + rr;
                float acc = b1m;
#pragma unroll 8
                for (int e = 0; e < 128; e++)
                    acc = fmaf(smf[EMBT + e * 33 + r], smf[PST + e * 33 + lane], acc);
                float v = fmaxf(acc, 0.f) * w2m;
#pragma unroll
                for (int o = 16; o > 0; o >>= 1)
                    v += __shfl_xor_sync(0xffffffffu, v, o);
                if (lane == 0) smf[PRIOW + r] = 1.f / (1.f + expf(-(v + b2s)));
            }
        }
        {
            float b2v = enb2[0];
            for (int pp = t2; pp < 1024; pp += 256) {
                int i = pp >> 5, j = pp & 31;
                float2 pi = s_pos2[i], pj = s_pos2[j];
                float dx = pi.x - pj.x, dy = pi.y - pj.y;
                float dist = sqrtf(dx * dx + dy * dy);
                float tq = dist * (1.f / 1000.f);
                float s = 0.f;
#pragma unroll
                for (int l = 0; l < 16; l++)
                    s = fmaf(fmaxf(fmaf(tq, __ldg(enw1 + l), __ldg(enb1 + l)), 0.f),
                             __ldg(enw2 + l), s);
                smf[EFFW + pp] = 0.85f + 0.13f / (1.f + expf(-(s + b2v)));
                smf[DISTW + pp] = dist;
            }
        }
        {
            uint4* bf = (uint4*)(smf + W2FRAG);
            for (int idx = t2; idx < 2048; idx += 256) {
                int tp = idx >> 8;
                int rem = idx & 255;
                int nt = rem >> 5, l2 = rem & 31;
                int n = nt * 8 + (l2 >> 2);
                int kb = tp * 16 + (l2 & 3);
                const float* wrow = fpw2 + n * 128 + kb;
                uint4 v;
                v.x = f2tf(__ldg(wrow));
                v.y = f2tf(__ldg(wrow + 4));
                v.z = f2tf(__ldg(wrow + 8));
                v.w = f2tf(__ldg(wrow + 12));
                bf[idx] = v;
            }
        }
    }
    float b3 = fpb3[0];
    __syncthreads();

    // ================= D. barrier-free mainloop ============================
    if (w < 8) {
        // ---- GEMM warps: inline-A tf32 mma, 16-row strip x 64 n -----------
        const int g = lane >> 2, l4 = lane & 3;
        const int sid = w >> 1;
        const int jl = (w & 1) * 16 + g;
        const int jh = jl + 8;
        const uint4* bfrag = (const uint4*)(smf + W2FRAG);

        for (int it = 0; it < 8; it++) {
            const int isend = 4 * it + sid;
            float ddl = smf[DISTW + isend * 32 + jl];
            float ddh = smf[DISTW + isend * 32 + jh];
            float acc[8][4];
#pragma unroll
            for (int nt = 0; nt < 8; nt++) {
                acc[nt][0] = 0.f; acc[nt][1] = 0.f;
                acc[nt][2] = 0.f; acc[nt][3] = 0.f;
            }
#pragma unroll
            for (int tp = 0; tp < 8; tp++) {
                int kb = tp * 16 + l4;
                float w0 = smf[W1DW + kb],      w1v = smf[W1DW + kb + 4];
                float w2v = smf[W1DW + kb + 8], w3v = smf[W1DW + kb + 12];
                float hi0 = smf[HIT + kb * 33 + isend];
                float hi1 = smf[HIT + (kb + 4) * 33 + isend];
                float hi2 = smf[HIT + (kb + 8) * 33 + isend];
                float hi3 = smf[HIT + (kb + 12) * 33 + isend];
                float hl0 = smf[HJT + kb * 33 + jl];
                float hl1 = smf[HJT + (kb + 4) * 33 + jl];
                float hl2 = smf[HJT + (kb + 8) * 33 + jl];
                float hl3 = smf[HJT + (kb + 12) * 33 + jl];
                float hh0 = smf[HJT + kb * 33 + jh];
                float hh1 = smf[HJT + (kb + 4) * 33 + jh];
                float hh2 = smf[HJT + (kb + 8) * 33 + jh];
                float hh3 = smf[HJT + (kb + 12) * 33 + jh];
                uint32_t a0 = f2tf(fmaxf(hi0 + fmaf(ddl, w0, hl0), 0.f));
                uint32_t a1 = f2tf(fmaxf(hi0 + fmaf(ddh, w0, hh0), 0.f));
                uint32_t a2 = f2tf(fmaxf(hi1 + fmaf(ddl, w1v, hl1), 0.f));
                uint32_t a3 = f2tf(fmaxf(hi1 + fmaf(ddh, w1v, hh1), 0.f));
                uint32_t a4 = f2tf(fmaxf(hi2 + fmaf(ddl, w2v, hl2), 0.f));
                uint32_t a5 = f2tf(fmaxf(hi2 + fmaf(ddh, w2v, hh2), 0.f));
                uint32_t a6 = f2tf(fmaxf(hi3 + fmaf(ddl, w3v, hl3), 0.f));
                uint32_t a7 = f2tf(fmaxf(hi3 + fmaf(ddh, w3v, hh3), 0.f));
                const uint4* bp = bfrag + tp * 256 + lane;
#pragma unroll
                for (int nt = 0; nt < 8; nt++) {
                    uint4 bv = bp[nt * 32];
                    MMA_TF32(acc[nt][0], acc[nt][1], acc[nt][2], acc[nt][3],
                             a0, a1, a2, a3, bv.x, bv.y);
                    MMA_TF32(acc[nt][0], acc[nt][1], acc[nt][2], acc[nt][3],
                             a4, a5, a6, a7, bv.z, bv.w);
                }
            }
            // epilogue: relu(+b2) dot w3 over 64 n, quad reduce, softplus
            float vlo = 0.f, vhi = 0.f;
#pragma unroll
            for (int nt = 0; nt < 8; nt++) {
                int n0 = nt * 8 + 2 * l4;
                float b2a = smf[B2FW + n0], b2b = smf[B2FW + n0 + 1];
                float w3a = smf[W3FW + n0], w3b = smf[W3FW + n0 + 1];
                vlo = fmaf(fmaxf(acc[nt][0] + b2a, 0.f), w3a, vlo);
                vlo = fmaf(fmaxf(acc[nt][1] + b2b, 0.f), w3b, vlo);
                vhi = fmaf(fmaxf(acc[nt][2] + b2a, 0.f), w3a, vhi);
                vhi = fmaf(fmaxf(acc[nt][3] + b2b, 0.f), w3b, vhi);
            }
            vlo += __shfl_xor_sync(0xffffffffu, vlo, 1);
            vlo += __shfl_xor_sync(0xffffffffu, vlo, 2);
            vhi += __shfl_xor_sync(0xffffffffu, vhi, 1);
            vhi += __shfl_xor_sync(0xffffffffu, vhi, 2);
            if (l4 == 0) {
                float x = vlo + b3;
                smf[PFW + isend * 32 + jl] = (x > 20.f) ? x : log1pf(expf(x));
                x = vhi + b3;
                smf[PFW + isend * 32 + jh] = (x > 20.f) ? x : log1pf(expf(x));
            }
        }
    } else {
        // ---- fill warps: stream all default output rows (evict-first) -----
        const int ft = t - 256;            // 0..255
        const float4 z4 = make_float4(0.f, 0.f, 0.f, 0.f);
        const float4 o4 = make_float4(1.f, 1.f, 1.f, 1.f);
        float4* outS4 = (float4*)out;
        float4* outE4 = (float4*)(out + MATSZ);
#pragma unroll 4
        for (int r = 0; r < 32; r++) {
            size_t rb = (size_t)s_gidx[r] * 1024;
#pragma unroll
            for (int q = 0; q < 4; q++) {
                stg_cs4(outS4 + rb + q * 256 + ft, z4);
                stg_cs4(outE4 + rb + q * 256 + ft, o4);
            }
        }
    }
    __syncthreads();

    // ================= E. greedy (warp 0, prefix-scan water-filling) =======
    if (w == 0) {
        float pr = smf[PRIOW + lane];
        int r = 0;
#pragma unroll
        for (int l = 0; l < KC; l++) {
            float q = smf[PRIOW + l];
            r += (q > pr) || (q == pr && l < lane);
        }
        s_ord[r] = lane;
        __syncwarp();
        int oj = s_ord[lane];
        float nets = smf[NETW + oj];
        float dn = nets;
        for (int i = 0; i < 32; i++) {
            int oi = s_ord[i];
            float A = fmaxf(__shfl_sync(0xffffffffu, nets, i), 0.f);
            float needed = -dn;
            float pf = smf[PFW + oi * 32 + oj];
            float cap = (needed > 0.f) ? fminf(needed, pf) : 0.f;
            float C = cap;
#pragma unroll
            for (int o = 1; o < 32; o <<= 1) {
                float x = __shfl_up_sync(0xffffffffu, C, o);
                if (lane >= o) C += x;
            }
            float Cprev = C - cap;
            float avail = A - Cprev;
            bool act = (avail > 0.f) && (needed > 0.f);
            float f = act ? fminf(fminf(avail, needed), pf) : 0.f;
            dn += f * smf[EFFW + oi * 32 + oj];
            smf[FLOWW + i * 32 + lane] = f;
            unsigned ab = __ballot_sync(0xffffffffu, act);
            if (lane == 0) s_actb[i] = ab;
        }
        smf[DNETW + lane] = dn;
        smf[NSRTW + lane] = nets;
    }
    __syncthreads();

    // ================= F. scatter (16 warps x 2 rows) ======================
    {
        float* out_sh = out;
        float* out_ef = out + MATSZ;
        float* out_sent = out + 2 * MATSZ + 1;
        float* out_recv = out_sent + NB;
        float* out_na = out_recv + NB;
        int oj = s_ord[lane];
        int gj = s_gidx[oj];
#pragma unroll
        for (int rr = 0; rr < 2; rr++) {
            int srow = w * 2 + rr;
            int oi = s_ord[srow];
            int gi = s_gidx[oi];
            float f = smf[FLOWW + srow * 32 + lane];
            unsigned ab = s_actb[srow];
            if ((ab >> lane) & 1u) {
                out_sh[(size_t)gi * NB + gj] = f;
                out_ef[(size_t)gi * NB + gj] = smf[EFFW + oi * 32 + oj];
            }
            float v = f;
#pragma unroll
            for (int o = 16; o > 0; o >>= 1) v += __shfl_xor_sync(0xffffffffu, v, o);
            if (lane == 0) {
                out_sent[gi] = v;
                float dnl = smf[DNETW + srow];
                out_recv[gi] = dnl - smf[NSRTW + srow];
                out_na[gi] = dnl;
                smf[RSENTW + srow] = v;
            }
        }
    }
    __syncthreads();

    // ================= G. per-cluster total + last-block global sum ========
    if (t == 0) {
        float tot = 0.f;
#pragma unroll
        for (int i = 0; i < 32; i++) tot += smf[RSENTW + i];
        d_partial[c] = tot;
        __threadfence();
        unsigned old = atomicAdd(&d_ticket, 1u);
        if (old == NC - 1) {
            __threadfence();
            float s0 = 0.f, s1 = 0.f, s2 = 0.f, s3 = 0.f;
#pragma unroll 8
            for (int q = 0; q < NC; q += 4) {
                s0 += __ldcg(d_partial + q);
                s1 += __ldcg(d_partial + q + 1);
                s2 += __ldcg(d_partial + q + 2);
                s3 += __ldcg(d_partial + q + 3);
            }
            out[2 * MATSZ] = (s0 + s1) + (s2 + s3);
            d_ticket = 0;
        }
    }
}

// ------------------------------------------------------------------------------
extern "C" void kernel_launch(void* const* d_in, const int* in_sizes, int n_in,
                              void* d_out, int out_size) {
    const float* emb   = (const float*)d_in[0];
    const float* gen   = (const float*)d_in[1];
    const float* cons  = (const float*)d_in[2];
    const float* pos   = (const float*)d_in[3];
    const float* fpw1  = (const float*)d_in[4];
    const float* fpb1  = (const float*)d_in[5];
    const float* fpw2  = (const float*)d_in[6];
    const float* fpb2  = (const float*)d_in[7];
    const float* fpw3  = (const float*)d_in[8];
    const float* fpb3  = (const float*)d_in[9];
    const float* enw1  = (const float*)d_in[10];
    const float* enb1  = (const float*)d_in[11];
    const float* enw2  = (const float*)d_in[12];
    const float* enb2  = (const float*)d_in[13];
    const float* psw1  = (const float*)d_in[14];
    const float* psb1  = (const float*)d_in[15];
    const float* psw2  = (const float*)d_in[16];
    const float* psb2  = (const float*)d_in[17];
    const int*   assign = (const int*)d_in[18];
    const int*   hour   = (n_in >= 21) ? (const int*)d_in[20] : nullptr;
    float* out = (float*)d_out;

    cudaFuncSetAttribute(mega_kernel,
                         cudaFuncAttributeMaxDynamicSharedMemorySize, SM_BYTES);

    mega_kernel<<<NC, NT, SM_BYTES>>>(emb, gen, cons, pos,
                                      fpw1, fpb1, fpw2, fpb2, fpw3, fpb3,
                                      enw1, enb1, enw2, enb2,
                                      psw1, psb1, psw2, psb2,
                                      assign, hour, out);
}